// round 2
// baseline (speedup 1.0000x reference)
#include <cuda_runtime.h>
#include <math.h>

#define TOK   32768          // b*NY*NX tokens
#define DM    1024
#define NSEQ  1024           // b*NY sequences
#define SEQ   32             // NX
#define NH    16
#define HD    64

typedef unsigned long long u64;

// ---------------- scratch (static device allocations) ----------------
static __device__ float g_X  [TOK * DM];        // router residual stream
static __device__ float g_H  [TOK * DM];        // LN out / attn out
static __device__ float g_QKV[TOK * 3 * DM];    // qkv, reused as masked xf
static __device__ float g_MLP[TOK * 4 * DM];    // mlp hidden
static __device__ float g_P1 [NSEQ * 16 * DM];  // pool factor-2 output
static __device__ float g_P2 [NSEQ * 8  * DM];  // pool factor-4 output
static __device__ int   g_CH [TOK];             // chosen (argmax)
static __device__ float g_MS [NSEQ];            // mask row-sums

// ---------------- helpers ----------------
__device__ __forceinline__ float gelu_tanh(float x) {
    const float c = 0.7978845608028654f;   // sqrt(2/pi)
    float x3 = x * x * x;
    return 0.5f * x * (1.0f + tanhf(c * (x + 0.044715f * x3)));
}

#define FFMA2(c, a, b) asm("fma.rn.f32x2 %0, %1, %2, %0;" : "+l"(c) : "l"(a), "l"(b))
#define UNPACK2(lo, hi, v) asm("mov.b64 {%0, %1}, %2;" : "=f"(lo), "=f"(hi) : "l"(v))

// ---------------- packed-f32x2 SGEMM: C = A(MxK) @ B(KxN) + bias [+epi] ----
// MODE 0: C = AB + bias
// MODE 1: C = gelu(AB + bias)
// MODE 2: C = res + AB + bias   (res may alias C)
template<int MODE>
__global__ __launch_bounds__(256, 2) void sgemm_k(
    const float* __restrict__ A, const float* __restrict__ B,
    const float* __restrict__ bias, const float* __restrict__ res,
    float* __restrict__ C, int M, int N, int K)
{
    // A tile stored with every value DUPLICATED: As[buf][k][2*m+{0,1}] = A(m,k)
    __shared__ float As[2][16][256];   // 32 KB
    __shared__ float Bs[2][16][128];   // 16 KB  (total 48 KB exactly)

    const int tid = threadIdx.x;
    const int m0 = blockIdx.y * 128;
    const int n0 = blockIdx.x * 128;

    const int tx = tid & 15;          // col group
    const int ty = tid >> 4;          // row group
    const int row0 = ty * 8;
    const int col0 = tx * 8;

    const int aRow = tid >> 2;        // 0..63
    const int aCol = (tid & 3) << 2;  // 0,4,8,12
    const int bRow = tid >> 5;        // 0..7
    const int bCol = (tid & 31) << 2; // 0..124

    u64 acc[8][4];
#pragma unroll
    for (int i = 0; i < 8; i++)
#pragma unroll
        for (int j = 0; j < 4; j++) acc[i][j] = 0ull;

    const float* Ag = A + (size_t)m0 * K;

    float4 pa0, pa1, pb0, pb1;

    // prologue load (k0 = 0)
    pa0 = *(const float4*)(Ag + (size_t)aRow        * K + aCol);
    pa1 = *(const float4*)(Ag + (size_t)(aRow + 64) * K + aCol);
    pb0 = *(const float4*)(B + (size_t)bRow       * N + n0 + bCol);
    pb1 = *(const float4*)(B + (size_t)(bRow + 8) * N + n0 + bCol);

    {   // store buffer 0
        float va0[4] = {pa0.x, pa0.y, pa0.z, pa0.w};
        float va1[4] = {pa1.x, pa1.y, pa1.z, pa1.w};
#pragma unroll
        for (int j = 0; j < 4; j++) {
            *(float2*)&As[0][aCol + j][2 * aRow]        = make_float2(va0[j], va0[j]);
            *(float2*)&As[0][aCol + j][2 * (aRow + 64)] = make_float2(va1[j], va1[j]);
        }
        *(float4*)&Bs[0][bRow][bCol]     = pb0;
        *(float4*)&Bs[0][bRow + 8][bCol] = pb1;
    }
    __syncthreads();

    int buf = 0;
    for (int k0 = 0; k0 < K; k0 += 16) {
        const bool more = (k0 + 16) < K;
        if (more) {
            int kn = k0 + 16;
            pa0 = *(const float4*)(Ag + (size_t)aRow        * K + kn + aCol);
            pa1 = *(const float4*)(Ag + (size_t)(aRow + 64) * K + kn + aCol);
            pb0 = *(const float4*)(B + (size_t)(kn + bRow)     * N + n0 + bCol);
            pb1 = *(const float4*)(B + (size_t)(kn + bRow + 8) * N + n0 + bCol);
        }

#pragma unroll
        for (int kk = 0; kk < 16; kk++) {
            const u64* ap = (const u64*)&As[buf][kk][2 * row0];
            const u64* bp = (const u64*)&Bs[buf][kk][col0];
            u64 a8[8], b4[4];
#pragma unroll
            for (int i = 0; i < 8; i++) a8[i] = ap[i];
#pragma unroll
            for (int j = 0; j < 4; j++) b4[j] = bp[j];
#pragma unroll
            for (int i = 0; i < 8; i++)
#pragma unroll
                for (int j = 0; j < 4; j++)
                    FFMA2(acc[i][j], a8[i], b4[j]);
        }

        if (more) {
            int nb = buf ^ 1;
            float va0[4] = {pa0.x, pa0.y, pa0.z, pa0.w};
            float va1[4] = {pa1.x, pa1.y, pa1.z, pa1.w};
#pragma unroll
            for (int j = 0; j < 4; j++) {
                *(float2*)&As[nb][aCol + j][2 * aRow]        = make_float2(va0[j], va0[j]);
                *(float2*)&As[nb][aCol + j][2 * (aRow + 64)] = make_float2(va1[j], va1[j]);
            }
            *(float4*)&Bs[nb][bRow][bCol]     = pb0;
            *(float4*)&Bs[nb][bRow + 8][bCol] = pb1;
            __syncthreads();
            buf = nb;
        }
    }

    float bv[8];
#pragma unroll
    for (int j = 0; j < 8; j++) bv[j] = bias[n0 + col0 + j];

#pragma unroll
    for (int i = 0; i < 8; i++) {
        size_t off = (size_t)(m0 + row0 + i) * N + n0 + col0;
        float v[8];
#pragma unroll
        for (int j = 0; j < 4; j++) UNPACK2(v[2 * j], v[2 * j + 1], acc[i][j]);
#pragma unroll
        for (int j = 0; j < 8; j++) {
            float t = v[j] + bv[j];
            if (MODE == 1) t = gelu_tanh(t);
            if (MODE == 2) t += res[off + j];
            v[j] = t;
        }
        *(float4*)(C + off)     = make_float4(v[0], v[1], v[2], v[3]);
        *(float4*)(C + off + 4) = make_float4(v[4], v[5], v[6], v[7]);
    }
}

// ---------------- LayerNorm (one block of 256 per token row) ----------------
__global__ __launch_bounds__(256) void ln_k(
    const float* __restrict__ X, const float* __restrict__ w,
    const float* __restrict__ b, float* __restrict__ out)
{
    const int row = blockIdx.x, tid = threadIdx.x;
    const int lane = tid & 31, wid = tid >> 5;
    __shared__ float red[8];

    float4 xv = ((const float4*)(X + (size_t)row * DM))[tid];
    float s = xv.x + xv.y + xv.z + xv.w;
#pragma unroll
    for (int o = 16; o > 0; o >>= 1) s += __shfl_xor_sync(0xffffffffu, s, o);
    if (lane == 0) red[wid] = s;
    __syncthreads();
    s = red[0] + red[1] + red[2] + red[3] + red[4] + red[5] + red[6] + red[7];
    float mean = s * (1.0f / 1024.0f);

    float dx = xv.x - mean, dy = xv.y - mean, dz = xv.z - mean, dw = xv.w - mean;
    float sq = dx * dx + dy * dy + dz * dz + dw * dw;
#pragma unroll
    for (int o = 16; o > 0; o >>= 1) sq += __shfl_xor_sync(0xffffffffu, sq, o);
    __syncthreads();
    if (lane == 0) red[wid] = sq;
    __syncthreads();
    sq = red[0] + red[1] + red[2] + red[3] + red[4] + red[5] + red[6] + red[7];
    float rstd = rsqrtf(sq * (1.0f / 1024.0f) + 1e-5f);

    float4 wv = ((const float4*)w)[tid];
    float4 bvv = ((const float4*)b)[tid];
    float4 o4;
    o4.x = dx * rstd * wv.x + bvv.x;
    o4.y = dy * rstd * wv.y + bvv.y;
    o4.z = dz * rstd * wv.z + bvv.z;
    o4.w = dw * rstd * wv.w + bvv.w;
    ((float4*)(out + (size_t)row * DM))[tid] = o4;
}

// ---------------- attention (one block per (seq, head)) ----------------
__global__ __launch_bounds__(256) void attn_k(
    const float* __restrict__ QKV, const float* __restrict__ mask,
    float* __restrict__ O)
{
    __shared__ float qs[SEQ * HD];
    __shared__ float ks[SEQ * (HD + 1)];
    __shared__ float vs[SEQ * (HD + 1)];
    __shared__ float sc[SEQ * SEQ];

    const int bseq = blockIdx.x >> 4;
    const int h    = blockIdx.x & 15;
    const int tid  = threadIdx.x;

    const float* base = QKV + (size_t)(bseq * SEQ) * 3072 + h * HD;
    for (int i = tid; i < SEQ * HD; i += 256) {
        int t = i >> 6, d = i & 63;
        qs[t * HD + d]       = base[(size_t)t * 3072 + d];
        ks[t * (HD + 1) + d] = base[(size_t)t * 3072 + 1024 + d];
        vs[t * (HD + 1) + d] = base[(size_t)t * 3072 + 2048 + d];
    }
    __syncthreads();

    for (int i = tid; i < SEQ * SEQ; i += 256) {
        int qi = i >> 5, ki = i & 31;
        float s = 0.0f;
#pragma unroll
        for (int d = 0; d < HD; d++) s += qs[qi * HD + d] * ks[ki * (HD + 1) + d];
        float mb = (mask[bseq * SEQ + ki] > 0.0f) ? 0.0f : -1e9f;
        sc[i] = s * 0.125f + mb;   // 1/sqrt(64)
    }
    __syncthreads();

    {   // softmax
        int wid = tid >> 5, lane = tid & 31;
        for (int r = wid; r < SEQ; r += 8) {
            float v = sc[r * SEQ + lane];
            float mx = v;
#pragma unroll
            for (int o = 16; o > 0; o >>= 1) mx = fmaxf(mx, __shfl_xor_sync(0xffffffffu, mx, o));
            float e = expf(v - mx);
            float su = e;
#pragma unroll
            for (int o = 16; o > 0; o >>= 1) su += __shfl_xor_sync(0xffffffffu, su, o);
            sc[r * SEQ + lane] = e / su;
        }
    }
    __syncthreads();

    for (int i = tid; i < SEQ * HD; i += 256) {
        int t = i >> 6, d = i & 63;
        float o = 0.0f;
#pragma unroll
        for (int k = 0; k < SEQ; k++) o += sc[t * SEQ + k] * vs[k * (HD + 1) + d];
        O[(size_t)(bseq * SEQ + t) * DM + h * HD + d] = o;
    }
}

// ---------------- logits + argmax (one warp per token) ----------------
__global__ void logits_k(const float* __restrict__ X, const float* __restrict__ W,
                         const float* __restrict__ bias, int* __restrict__ chosen)
{
    int gtid = blockIdx.x * blockDim.x + threadIdx.x;
    int row  = gtid >> 5;
    int lane = threadIdx.x & 31;
    if (row >= TOK) return;
    const float* xr = X + (size_t)row * DM;
    float a0 = 0, a1 = 0, a2 = 0;
    for (int j = lane; j < DM; j += 32) {
        float x = xr[j];
        a0 += x * W[j * 3 + 0];
        a1 += x * W[j * 3 + 1];
        a2 += x * W[j * 3 + 2];
    }
#pragma unroll
    for (int o = 16; o > 0; o >>= 1) {
        a0 += __shfl_xor_sync(0xffffffffu, a0, o);
        a1 += __shfl_xor_sync(0xffffffffu, a1, o);
        a2 += __shfl_xor_sync(0xffffffffu, a2, o);
    }
    if (lane == 0) {
        a0 += bias[0]; a1 += bias[1]; a2 += bias[2];
        int idx = 0; float best = a0;
        if (a1 > best) { best = a1; idx = 1; }
        if (a2 > best) { best = a2; idx = 2; }
        chosen[row] = idx;
    }
}

// ---------------- small utility kernels ----------------
__global__ void maskmul_k(const float4* __restrict__ x, const float* __restrict__ mask,
                          float4* __restrict__ out, int n4) {
    int i = blockIdx.x * 256 + threadIdx.x;
    if (i < n4) {
        float m = mask[i >> 8];   // 256 float4 per 1024-float token row
        float4 v = x[i];
        v.x *= m; v.y *= m; v.z *= m; v.w *= m;
        out[i] = v;
    }
}

__global__ void msum_k(const float* __restrict__ mask, float* __restrict__ ms) {
    int b = blockIdx.x, lane = threadIdx.x;
    float m = mask[b * SEQ + lane];
#pragma unroll
    for (int o = 16; o > 0; o >>= 1) m += __shfl_xor_sync(0xffffffffu, m, o);
    if (lane == 0) ms[b] = m;
}

__global__ void compress_k(const int* __restrict__ chosen, const float* __restrict__ mask,
                           float* __restrict__ comp) {
    int b = blockIdx.x, lane = threadIdx.x;
    float c = (float)chosen[b * SEQ + lane] / 3.0f;
    float m = mask[b * SEQ + lane];
    float num = c * m, den = m;
#pragma unroll
    for (int o = 16; o > 0; o >>= 1) {
        num += __shfl_xor_sync(0xffffffffu, num, o);
        den += __shfl_xor_sync(0xffffffffu, den, o);
    }
    if (lane == 0) comp[b] = num / den;
}

// ---------------- final assembly: outputs + masks ----------------
__global__ __launch_bounds__(256) void assemble_k(
    const float* __restrict__ x, const float* __restrict__ mask,
    const int* __restrict__ chosen, const float* __restrict__ msum,
    const float* __restrict__ P1, const float* __restrict__ P2,
    const float* __restrict__ emb,
    float* __restrict__ out, float* __restrict__ masks_out)
{
    const int r = blockIdx.x;
    const int b = r >> 5, pos = r & 31;
    const int tid = threadIdx.x;
    const int c = chosen[r];
    const float ms = msum[b];

    float4* o4 = (float4*)(out + (size_t)r * DM);
    float maskv;

    if (c == 0) {
        o4[tid] = ((const float4*)(x + (size_t)r * DM))[tid];
        maskv = mask[r];
    } else if (c == 1) {
        float nm = ((float)pos < ms * 0.5f) ? 1.0f : 0.0f;
        float4 e = ((const float4*)emb)[tid];
        float4 pv = make_float4(0, 0, 0, 0);
        if (pos < 16) pv = ((const float4*)(P1 + (size_t)(b * 16 + pos) * DM))[tid];
        o4[tid] = make_float4(pv.x * nm + e.x, pv.y * nm + e.y,
                              pv.z * nm + e.z, pv.w * nm + e.w);
        maskv = nm;
    } else {
        float nm = ((float)pos < ms * 0.25f) ? 1.0f : 0.0f;
        float4 e = ((const float4*)(emb + DM))[tid];
        float4 pv = make_float4(0, 0, 0, 0);
        if (pos < 8) pv = ((const float4*)(P2 + (size_t)(b * 8 + pos) * DM))[tid];
        o4[tid] = make_float4(pv.x * nm + e.x, pv.y * nm + e.y,
                              pv.z * nm + e.z, pv.w * nm + e.w);
        maskv = nm;
    }
    if (tid == 0) masks_out[r] = maskv;
}

// ---------------- launch ----------------
extern "C" void kernel_launch(void* const* d_in, const int* in_sizes, int n_in,
                              void* d_out, int out_size)
{
    const float* x     = (const float*)d_in[0];
    const float* mask  = (const float*)d_in[1];
    const float* ln1_w = (const float*)d_in[2];
    const float* ln1_b = (const float*)d_in[3];
    const float* wqkv  = (const float*)d_in[4];
    const float* bqkv  = (const float*)d_in[5];
    const float* wo    = (const float*)d_in[6];
    const float* bo    = (const float*)d_in[7];
    const float* ln2_w = (const float*)d_in[8];
    const float* ln2_b = (const float*)d_in[9];
    const float* w1    = (const float*)d_in[10];
    const float* b1    = (const float*)d_in[11];
    const float* w2    = (const float*)d_in[12];
    const float* b2    = (const float*)d_in[13];
    const float* rfw   = (const float*)d_in[14];
    const float* rfb   = (const float*)d_in[15];
    const float* p2w   = (const float*)d_in[16];
    const float* p2b   = (const float*)d_in[17];
    const float* p4w   = (const float*)d_in[18];
    const float* p4b   = (const float*)d_in[19];
    const float* femb  = (const float*)d_in[20];

    float *X, *H, *QKV, *MLP, *P1, *P2, *MS;
    int* CH;
    cudaGetSymbolAddress((void**)&X,   g_X);
    cudaGetSymbolAddress((void**)&H,   g_H);
    cudaGetSymbolAddress((void**)&QKV, g_QKV);
    cudaGetSymbolAddress((void**)&MLP, g_MLP);
    cudaGetSymbolAddress((void**)&P1,  g_P1);
    cudaGetSymbolAddress((void**)&P2,  g_P2);
    cudaGetSymbolAddress((void**)&MS,  g_MS);
    cudaGetSymbolAddress((void**)&CH,  g_CH);

    const int n4 = TOK * DM / 4;

    for (int i = 0; i < 2; i++) {
        const float* Xin = (i == 0) ? x : X;   // layer 0 reads input directly
        ln_k<<<TOK, 256>>>(Xin, ln1_w + i * DM, ln1_b + i * DM, H);
        sgemm_k<0><<<dim3(3072 / 128, TOK / 128), 256>>>(
            H, wqkv + (size_t)i * DM * 3072, bqkv + i * 3072, nullptr, QKV, TOK, 3072, DM);
        attn_k<<<NSEQ * NH, 256>>>(QKV, mask, H);
        sgemm_k<2><<<dim3(DM / 128, TOK / 128), 256>>>(
            H, wo + (size_t)i * DM * DM, bo + i * DM, Xin, X, TOK, DM, DM);
        ln_k<<<TOK, 256>>>(X, ln2_w + i * DM, ln2_b + i * DM, H);
        sgemm_k<1><<<dim3(4096 / 128, TOK / 128), 256>>>(
            H, w1 + (size_t)i * DM * 4096, b1 + i * 4096, nullptr, MLP, TOK, 4096, DM);
        sgemm_k<2><<<dim3(DM / 128, TOK / 128), 256>>>(
            MLP, w2 + (size_t)i * 4096 * DM, b2 + i * DM, X, X, TOK, DM, 4096);
    }

    logits_k<<<TOK / 8, 256>>>(X, rfw, rfb, CH);

    maskmul_k<<<n4 / 256, 256>>>((const float4*)x, mask, (float4*)QKV, n4);
    sgemm_k<0><<<dim3(DM / 128, 16384 / 128), 256>>>(QKV, p2w, p2b, nullptr, P1, 16384, DM, 2048);
    sgemm_k<0><<<dim3(DM / 128, 8192 / 128), 256>>>(QKV, p4w, p4b, nullptr, P2, 8192, DM, 4096);

    msum_k<<<NSEQ, 32>>>(mask, MS);

    float* out = (float*)d_out;
    assemble_k<<<TOK, 256>>>(x, mask, CH, MS, P1, P2, femb, out, out + (size_t)TOK * DM);
    compress_k<<<NSEQ, 32>>>(CH, mask, out + (size_t)TOK * DM + TOK);
}

// round 7
// speedup vs baseline: 1.5435x; 1.5435x over previous
#include <cuda_runtime.h>
#include <cuda_bf16.h>
#include <math.h>
#include <stdint.h>

#define TOK   32768
#define DM    1024
#define NSEQ  1024
#define SEQ   32
#define NH    16
#define HD    64
#define CMAX  256          // max sequences recomputed exactly
#define TAU   1e-3f        // argmax margin threshold

// ---------------- scratch ----------------
static __device__ float g_X  [TOK * DM];
static __device__ float g_H  [TOK * DM];
static __device__ float g_QKV[TOK * 3 * DM];
static __device__ float g_MLP[TOK * 4 * DM];
static __device__ float g_P1 [NSEQ * 16 * DM];
static __device__ float g_P2 [NSEQ * 8  * DM];
static __device__ int   g_CH [TOK];
static __device__ float g_MS [NSEQ];

// selective exact-recompute state
static __device__ int   g_FLAG[NSEQ];
static __device__ int   g_LIST[CMAX];
static __device__ int   g_CNT [1];
static __device__ float g_XR  [CMAX * SEQ * DM];
static __device__ float g_HR  [CMAX * SEQ * DM];
static __device__ float g_QKVR[CMAX * SEQ * 3 * DM];
static __device__ float g_MLPR[CMAX * SEQ * 4 * DM];

// fragment-major bf16 weight planes [layer][plane h/m/l]
static __device__ __nv_bfloat16 g_qkvB[2][3][3072 * 1024];
static __device__ __nv_bfloat16 g_woB [2][3][1024 * 1024];
static __device__ __nv_bfloat16 g_w1B [2][3][4096 * 1024];
static __device__ __nv_bfloat16 g_w2B [2][3][1024 * 4096];
static __device__ __nv_bfloat16 g_p2B [3][1024 * 2048];
static __device__ __nv_bfloat16 g_p4B [3][1024 * 4096];

// ---------------- helpers ----------------
__device__ __forceinline__ float gelu_tanh(float x) {
    const float c = 0.7978845608028654f;
    float x3 = x * x * x;
    return 0.5f * x * (1.0f + tanhf(c * (x + 0.044715f * x3)));
}
__device__ __forceinline__ uint32_t pack2(__nv_bfloat16 a, __nv_bfloat16 b) {
    __nv_bfloat162 t; t.x = a; t.y = b;
    return *reinterpret_cast<uint32_t*>(&t);
}
__device__ __forceinline__ uint32_t smem_u32(const void* p) {
    uint32_t a;
    asm("{ .reg .u64 t; cvta.to.shared.u64 t, %1; cvt.u32.u64 %0, t; }" : "=r"(a) : "l"(p));
    return a;
}
__device__ __forceinline__ void cp_async16(uint32_t saddr, const void* g) {
    asm volatile("cp.async.ca.shared.global [%0], [%1], 16;" :: "r"(saddr), "l"(g));
}
#define CP_COMMIT() asm volatile("cp.async.commit_group;" ::: "memory")
#define CP_WAIT0()  asm volatile("cp.async.wait_group 0;" ::: "memory")

#define MMA_BF16(cd, a, b) \
    asm volatile("mma.sync.aligned.m16n8k16.row.col.f32.bf16.bf16.f32 " \
        "{%0,%1,%2,%3}, {%4,%5,%6,%7}, {%8,%9}, {%0,%1,%2,%3};" \
        : "+f"((cd)[0]), "+f"((cd)[1]), "+f"((cd)[2]), "+f"((cd)[3]) \
        : "r"((a).x), "r"((a).y), "r"((a).z), "r"((a).w), \
          "r"((b).x), "r"((b).y))

// ============ weight preprocess: W[K][N] -> fragment-major bf16 h/m/l ======
__global__ __launch_bounds__(256) void bsplit_k(
    const float* __restrict__ W,
    __nv_bfloat16* __restrict__ Th, __nv_bfloat16* __restrict__ Tm,
    __nv_bfloat16* __restrict__ Tl, int K, int N)
{
    int idx = blockIdx.x * 256 + threadIdx.x;   // over K*N/2
    int n = idx % N;
    int k = (idx / N) * 2;
    float v0 = W[(size_t)k * N + n];
    float v1 = W[(size_t)(k + 1) * N + n];

    __nv_bfloat16 h0 = __float2bfloat16(v0); float r0 = v0 - __bfloat162float(h0);
    __nv_bfloat16 m0 = __float2bfloat16(r0); r0 -= __bfloat162float(m0);
    __nv_bfloat16 l0 = __float2bfloat16(r0);
    __nv_bfloat16 h1 = __float2bfloat16(v1); float r1 = v1 - __bfloat162float(h1);
    __nv_bfloat16 m1 = __float2bfloat16(r1); r1 -= __bfloat162float(m1);
    __nv_bfloat16 l1 = __float2bfloat16(r1);

    size_t t = (size_t)(n >> 3) * (K >> 4) + (k >> 4);
    int lane = (n & 7) * 4 + ((k & 7) >> 1);
    int reg  = (k & 15) >> 3;
    size_t o = t * 64 + lane * 2 + reg;
    ((uint32_t*)Th)[o] = pack2(h0, h1);
    ((uint32_t*)Tm)[o] = pack2(m0, m1);
    ((uint32_t*)Tl)[o] = pack2(l0, l1);
}

// ============ bf16x6 tensor-core GEMM (fast path) ==========================
#define BK     32
#define SA_PL  2048
#define SB_OFF 6144
#define SB_PL  2048
#define STG    12288
#define TG_SMEM (2 * STG * 4)

__device__ __forceinline__ void stsA(uint32_t* smu, uint32_t base, int tid,
                                     const float4* av) {
#pragma unroll
    for (int p = 0; p < 4; p++) {
        int id = tid + p * 256;
        int row = id >> 3, c4 = (id & 7) << 2;
        int mt = row >> 4, r = row & 15;
        int kt = c4 >> 4;
        int reg = (r >> 3) | (((c4 >> 3) & 1) << 1);
        int lane0 = (r & 7) * 4 + ((c4 & 7) >> 1);
        uint32_t tbase = base + (mt * 2 + kt) * 128;
        float v[4] = {av[p].x, av[p].y, av[p].z, av[p].w};
#pragma unroll
        for (int q = 0; q < 2; q++) {
            float e0 = v[2 * q], e1 = v[2 * q + 1];
            __nv_bfloat16 h0 = __float2bfloat16(e0); float s0 = e0 - __bfloat162float(h0);
            __nv_bfloat16 m0 = __float2bfloat16(s0); s0 -= __bfloat162float(m0);
            __nv_bfloat16 l0 = __float2bfloat16(s0);
            __nv_bfloat16 h1 = __float2bfloat16(e1); float s1 = e1 - __bfloat162float(h1);
            __nv_bfloat16 m1 = __float2bfloat16(s1); s1 -= __bfloat162float(m1);
            __nv_bfloat16 l1 = __float2bfloat16(s1);
            uint32_t off = (uint32_t)((lane0 + q) * 4 + reg);
            smu[tbase + off]             = pack2(h0, h1);
            smu[tbase + SA_PL + off]     = pack2(m0, m1);
            smu[tbase + 2 * SA_PL + off] = pack2(l0, l1);
        }
    }
}

template<int MODE>
__global__ __launch_bounds__(256, 1) void tgemm_k(
    const float* __restrict__ A,
    const __nv_bfloat16* __restrict__ Bhg, const __nv_bfloat16* __restrict__ Bmg,
    const __nv_bfloat16* __restrict__ Blg,
    const float* __restrict__ bias, const float* __restrict__ res,
    float* __restrict__ C, int M, int N, int K)
{
    extern __shared__ float sm[];
    uint32_t* smu = (uint32_t*)sm;
    const uint32_t smb = smem_u32(sm);

    const int tid = threadIdx.x;
    const int wid = tid >> 5, lane = tid & 31;
    const int wm = wid & 1, wn = wid >> 1;
    const int m0 = blockIdx.y * 128, n0 = blockIdx.x * 128;
    const int K16 = K >> 4;

    float acc[4][4][4];
#pragma unroll
    for (int i = 0; i < 4; i++)
#pragma unroll
        for (int j = 0; j < 4; j++)
#pragma unroll
            for (int q = 0; q < 4; q++) acc[i][j][q] = 0.0f;

    const int nst = K / BK;
    float4 aval[4];

#pragma unroll
    for (int p = 0; p < 4; p++) {
        int id = tid + p * 256;
        int row = id >> 3, c4 = (id & 7) << 2;
        aval[p] = *(const float4*)(A + (size_t)(m0 + row) * K + c4);
    }
#pragma unroll
    for (int p = 0; p < 6; p++) {
        int id = tid + p * 256;
        int plane = id >> 9, rem = id & 511;
        int tile = rem >> 4, f = rem & 15;
        int ntl = tile >> 1, ktl = tile & 1;
        const __nv_bfloat16* src = (plane == 0) ? Bhg : (plane == 1) ? Bmg : Blg;
        size_t gt = (size_t)((n0 >> 3) + ntl) * K16 + ktl;
        cp_async16(smb + (uint32_t)(SB_OFF + plane * SB_PL + tile * 64 + f * 4) * 4,
                   (const char*)src + gt * 256 + f * 16);
    }
    CP_COMMIT();
    stsA(smu, 0, tid, aval);
    CP_WAIT0();
    __syncthreads();

    for (int st = 0; st < nst; st++) {
        const int buf = st & 1;
        const bool more = (st + 1) < nst;
        if (more) {
            const int k0n = (st + 1) * BK;
#pragma unroll
            for (int p = 0; p < 4; p++) {
                int id = tid + p * 256;
                int row = id >> 3, c4 = (id & 7) << 2;
                aval[p] = *(const float4*)(A + (size_t)(m0 + row) * K + k0n + c4);
            }
            const uint32_t nbase = (uint32_t)((buf ^ 1) * STG);
#pragma unroll
            for (int p = 0; p < 6; p++) {
                int id = tid + p * 256;
                int plane = id >> 9, rem = id & 511;
                int tile = rem >> 4, f = rem & 15;
                int ntl = tile >> 1, ktl = tile & 1;
                const __nv_bfloat16* src = (plane == 0) ? Bhg : (plane == 1) ? Bmg : Blg;
                size_t gt = (size_t)((n0 >> 3) + ntl) * K16 + (k0n >> 4) + ktl;
                cp_async16(smb + (nbase + SB_OFF + plane * SB_PL + tile * 64 + f * 4) * 4,
                           (const char*)src + gt * 256 + f * 16);
            }
            CP_COMMIT();
        }

        const uint32_t ab = (uint32_t)(buf * STG);
        const uint32_t bb = ab + SB_OFF;
#pragma unroll
        for (int kt = 0; kt < 2; kt++) {
            uint4 Ah[4], Am[4], Al[4];
            uint2 Bh[4], Bm[4], Bl[4];
#pragma unroll
            for (int mt = 0; mt < 4; mt++)
                Ah[mt] = *((const uint4*)(smu + ab + ((wm * 4 + mt) * 2 + kt) * 128) + lane);
#pragma unroll
            for (int nt = 0; nt < 4; nt++)
                Bh[nt] = *((const uint2*)(smu + bb + ((wn * 4 + nt) * 2 + kt) * 64) + lane);
#pragma unroll
            for (int mt = 0; mt < 4; mt++)
#pragma unroll
                for (int nt = 0; nt < 4; nt++) MMA_BF16(acc[mt][nt], Ah[mt], Bh[nt]);

#pragma unroll
            for (int nt = 0; nt < 4; nt++)
                Bm[nt] = *((const uint2*)(smu + bb + SB_PL + ((wn * 4 + nt) * 2 + kt) * 64) + lane);
#pragma unroll
            for (int mt = 0; mt < 4; mt++)
#pragma unroll
                for (int nt = 0; nt < 4; nt++) MMA_BF16(acc[mt][nt], Ah[mt], Bm[nt]);

#pragma unroll
            for (int mt = 0; mt < 4; mt++)
                Am[mt] = *((const uint4*)(smu + ab + SA_PL + ((wm * 4 + mt) * 2 + kt) * 128) + lane);
#pragma unroll
            for (int mt = 0; mt < 4; mt++)
#pragma unroll
                for (int nt = 0; nt < 4; nt++) MMA_BF16(acc[mt][nt], Am[mt], Bh[nt]);
#pragma unroll
            for (int mt = 0; mt < 4; mt++)
#pragma unroll
                for (int nt = 0; nt < 4; nt++) MMA_BF16(acc[mt][nt], Am[mt], Bm[nt]);

#pragma unroll
            for (int nt = 0; nt < 4; nt++)
                Bl[nt] = *((const uint2*)(smu + bb + 2 * SB_PL + ((wn * 4 + nt) * 2 + kt) * 64) + lane);
#pragma unroll
            for (int mt = 0; mt < 4; mt++)
#pragma unroll
                for (int nt = 0; nt < 4; nt++) MMA_BF16(acc[mt][nt], Ah[mt], Bl[nt]);

#pragma unroll
            for (int mt = 0; mt < 4; mt++)
                Al[mt] = *((const uint4*)(smu + ab + 2 * SA_PL + ((wm * 4 + mt) * 2 + kt) * 128) + lane);
#pragma unroll
            for (int mt = 0; mt < 4; mt++)
#pragma unroll
                for (int nt = 0; nt < 4; nt++) MMA_BF16(acc[mt][nt], Al[mt], Bh[nt]);
        }

        if (more) stsA(smu, (uint32_t)((buf ^ 1) * STG), tid, aval);
        CP_WAIT0();
        __syncthreads();
    }

    const int r0 = lane >> 2, cc = (lane & 3) * 2;
#pragma unroll
    for (int mt = 0; mt < 4; mt++) {
#pragma unroll
        for (int nt = 0; nt < 4; nt++) {
            int gm = m0 + wm * 64 + mt * 16 + r0;
            int gn = n0 + wn * 32 + nt * 8 + cc;
            float b0 = bias[gn], b1 = bias[gn + 1];
            float v0 = acc[mt][nt][0] + b0, v1 = acc[mt][nt][1] + b1;
            float v2 = acc[mt][nt][2] + b0, v3 = acc[mt][nt][3] + b1;
            size_t o0 = (size_t)gm * N + gn;
            size_t o1 = (size_t)(gm + 8) * N + gn;
            if (MODE == 1) {
                v0 = gelu_tanh(v0); v1 = gelu_tanh(v1);
                v2 = gelu_tanh(v2); v3 = gelu_tanh(v3);
            }
            if (MODE == 2) {
                v0 += res[o0]; v1 += res[o0 + 1];
                v2 += res[o1]; v3 += res[o1 + 1];
            }
            *(float2*)(C + o0) = make_float2(v0, v1);
            *(float2*)(C + o1) = make_float2(v2, v3);
        }
    }
}

// ============ exact FFMA SGEMM (verbatim R1 semantics) + early exit ========
template<int MODE>
__global__ __launch_bounds__(256) void fgemm_k(
    const float* __restrict__ A, const float* __restrict__ B,
    const float* __restrict__ bias, const float* __restrict__ res,
    float* __restrict__ C, int M, int N, int K, const int* __restrict__ cntp)
{
    const int m0 = blockIdx.y * 128;
    if (cntp) {
        int c = *cntp; if (c > CMAX) c = CMAX;
        if ((m0 >> 5) >= c * 1) { if (m0 >= c * SEQ) return; }
    }
    __shared__ float As[16][128];
    __shared__ float Bs[16][128];

    const int tid = threadIdx.x;
    const int n0 = blockIdx.x * 128;

    const int tx = tid & 15;
    const int ty = tid >> 4;
    const int row0 = ty * 8;
    const int col0 = tx * 8;

    const int aRow = tid >> 2;
    const int aCol = (tid & 3) << 2;
    const int bRow = tid >> 5;
    const int bCol = (tid & 31) << 2;

    float acc[8][8];
#pragma unroll
    for (int i = 0; i < 8; i++)
#pragma unroll
        for (int j = 0; j < 8; j++) acc[i][j] = 0.0f;

    const float* Ag = A + (size_t)m0 * K;

    for (int k0 = 0; k0 < K; k0 += 16) {
        float4 a0 = *(const float4*)(Ag + (size_t)aRow        * K + k0 + aCol);
        float4 a1 = *(const float4*)(Ag + (size_t)(aRow + 64) * K + k0 + aCol);
        As[aCol + 0][aRow] = a0.x; As[aCol + 1][aRow] = a0.y;
        As[aCol + 2][aRow] = a0.z; As[aCol + 3][aRow] = a0.w;
        As[aCol + 0][aRow + 64] = a1.x; As[aCol + 1][aRow + 64] = a1.y;
        As[aCol + 2][aRow + 64] = a1.z; As[aCol + 3][aRow + 64] = a1.w;

        float4 b0 = *(const float4*)(B + (size_t)(k0 + bRow)     * N + n0 + bCol);
        float4 b1 = *(const float4*)(B + (size_t)(k0 + bRow + 8) * N + n0 + bCol);
        *(float4*)&Bs[bRow][bCol]     = b0;
        *(float4*)&Bs[bRow + 8][bCol] = b1;

        __syncthreads();

#pragma unroll
        for (int kk = 0; kk < 16; kk++) {
            float a[8], b[8];
            *(float4*)(a)     = *(const float4*)&As[kk][row0];
            *(float4*)(a + 4) = *(const float4*)&As[kk][row0 + 4];
            *(float4*)(b)     = *(const float4*)&Bs[kk][col0];
            *(float4*)(b + 4) = *(const float4*)&Bs[kk][col0 + 4];
#pragma unroll
            for (int i = 0; i < 8; i++)
#pragma unroll
                for (int j = 0; j < 8; j++)
                    acc[i][j] += a[i] * b[j];
        }
        __syncthreads();
    }

    float bv[8];
#pragma unroll
    for (int j = 0; j < 8; j++) bv[j] = bias[n0 + col0 + j];

#pragma unroll
    for (int i = 0; i < 8; i++) {
        size_t off = (size_t)(m0 + row0 + i) * N + n0 + col0;
        float v[8];
#pragma unroll
        for (int j = 0; j < 8; j++) {
            float t = acc[i][j] + bv[j];
            if (MODE == 1) t = gelu_tanh(t);
            if (MODE == 2) t += res[off + j];
            v[j] = t;
        }
        *(float4*)(C + off)     = make_float4(v[0], v[1], v[2], v[3]);
        *(float4*)(C + off + 4) = make_float4(v[4], v[5], v[6], v[7]);
    }
}

// ---------------- LayerNorm (shared by fast + exact paths) ----------------
__global__ __launch_bounds__(256) void ln_k(
    const float* __restrict__ X, const float* __restrict__ w,
    const float* __restrict__ b, float* __restrict__ out,
    const int* __restrict__ cntp)
{
    const int row = blockIdx.x;
    if (cntp) {
        int c = *cntp; if (c > CMAX) c = CMAX;
        if (row >= c * SEQ) return;
    }
    const int tid = threadIdx.x;
    const int lane = tid & 31, wid = tid >> 5;
    __shared__ float red[8];

    float4 xv = ((const float4*)(X + (size_t)row * DM))[tid];
    float s = xv.x + xv.y + xv.z + xv.w;
#pragma unroll
    for (int o = 16; o > 0; o >>= 1) s += __shfl_xor_sync(0xffffffffu, s, o);
    if (lane == 0) red[wid] = s;
    __syncthreads();
    s = red[0] + red[1] + red[2] + red[3] + red[4] + red[5] + red[6] + red[7];
    float mean = s * (1.0f / 1024.0f);

    float dx = xv.x - mean, dy = xv.y - mean, dz = xv.z - mean, dw = xv.w - mean;
    float sq = dx * dx + dy * dy + dz * dz + dw * dw;
#pragma unroll
    for (int o = 16; o > 0; o >>= 1) sq += __shfl_xor_sync(0xffffffffu, sq, o);
    __syncthreads();
    if (lane == 0) red[wid] = sq;
    __syncthreads();
    sq = red[0] + red[1] + red[2] + red[3] + red[4] + red[5] + red[6] + red[7];
    float rstd = rsqrtf(sq * (1.0f / 1024.0f) + 1e-5f);

    float4 wv = ((const float4*)w)[tid];
    float4 bv = ((const float4*)b)[tid];
    float4 o4;
    o4.x = dx * rstd * wv.x + bv.x;
    o4.y = dy * rstd * wv.y + bv.y;
    o4.z = dz * rstd * wv.z + bv.z;
    o4.w = dw * rstd * wv.w + bv.w;
    ((float4*)(out + (size_t)row * DM))[tid] = o4;
}

// ---------------- attention (fast: seqlist == nullptr) ----------------
__global__ __launch_bounds__(256) void attn_k(
    const float* __restrict__ QKV, const float* __restrict__ mask,
    float* __restrict__ O, const int* __restrict__ seqlist,
    const int* __restrict__ cntp)
{
    __shared__ float qs[SEQ * HD];
    __shared__ float ks[SEQ * (HD + 1)];
    __shared__ float vs[SEQ * (HD + 1)];
    __shared__ float sc[SEQ * SEQ];

    const int bseq = blockIdx.x >> 4;
    const int h    = blockIdx.x & 15;
    const int tid  = threadIdx.x;

    int mseq = bseq;
    if (cntp) {
        int c = *cntp; if (c > CMAX) c = CMAX;
        if (bseq >= c) return;
        mseq = seqlist[bseq];
    }

    const float* base = QKV + (size_t)(bseq * SEQ) * 3072 + h * HD;
    for (int i = tid; i < SEQ * HD; i += 256) {
        int t = i >> 6, d = i & 63;
        qs[t * HD + d]       = base[(size_t)t * 3072 + d];
        ks[t * (HD + 1) + d] = base[(size_t)t * 3072 + 1024 + d];
        vs[t * (HD + 1) + d] = base[(size_t)t * 3072 + 2048 + d];
    }
    __syncthreads();

    for (int i = tid; i < SEQ * SEQ; i += 256) {
        int qi = i >> 5, ki = i & 31;
        float s = 0.0f;
#pragma unroll
        for (int d = 0; d < HD; d++) s += qs[qi * HD + d] * ks[ki * (HD + 1) + d];
        float mb = (mask[mseq * SEQ + ki] > 0.0f) ? 0.0f : -1e9f;
        sc[i] = s * 0.125f + mb;
    }
    __syncthreads();

    {
        int wid = tid >> 5, lane = tid & 31;
        for (int r = wid; r < SEQ; r += 8) {
            float v = sc[r * SEQ + lane];
            float mx = v;
#pragma unroll
            for (int o = 16; o > 0; o >>= 1) mx = fmaxf(mx, __shfl_xor_sync(0xffffffffu, mx, o));
            float e = expf(v - mx);
            float su = e;
#pragma unroll
            for (int o = 16; o > 0; o >>= 1) su += __shfl_xor_sync(0xffffffffu, su, o);
            sc[r * SEQ + lane] = e / su;
        }
    }
    __syncthreads();

    for (int i = tid; i < SEQ * HD; i += 256) {
        int t = i >> 6, d = i & 63;
        float o = 0.0f;
#pragma unroll
        for (int k = 0; k < SEQ; k++) o += sc[t * SEQ + k] * vs[k * (HD + 1) + d];
        O[(size_t)(bseq * SEQ + t) * DM + h * HD + d] = o;
    }
}

// ---------------- logits + argmax + margin flagging ----------------
__global__ void logits_margin_k(const float* __restrict__ X, const float* __restrict__ W,
                                const float* __restrict__ bias, int* __restrict__ chosen,
                                int* __restrict__ flag, int* __restrict__ list,
                                int* __restrict__ cnt)
{
    int gtid = blockIdx.x * blockDim.x + threadIdx.x;
    int row  = gtid >> 5;
    int lane = threadIdx.x & 31;
    if (row >= TOK) return;
    const float* xr = X + (size_t)row * DM;
    float a0 = 0, a1 = 0, a2 = 0;
    for (int j = lane; j < DM; j += 32) {
        float x = xr[j];
        a0 += x * W[j * 3 + 0];
        a1 += x * W[j * 3 + 1];
        a2 += x * W[j * 3 + 2];
    }
#pragma unroll
    for (int o = 16; o > 0; o >>= 1) {
        a0 += __shfl_xor_sync(0xffffffffu, a0, o);
        a1 += __shfl_xor_sync(0xffffffffu, a1, o);
        a2 += __shfl_xor_sync(0xffffffffu, a2, o);
    }
    if (lane == 0) {
        a0 += bias[0]; a1 += bias[1]; a2 += bias[2];
        int idx = 0; float best = a0;
        if (a1 > best) { best = a1; idx = 1; }
        if (a2 > best) { best = a2; idx = 2; }
        chosen[row] = idx;
        // second-best
        float s2 = -3.4e38f;
        if (idx != 0 && a0 > s2) s2 = a0;
        if (idx != 1 && a1 > s2) s2 = a1;
        if (idx != 2 && a2 > s2) s2 = a2;
        if (best - s2 < TAU) {
            int seq = row >> 5;
            if (atomicExch(&flag[seq], 1) == 0) {
                int p = atomicAdd(cnt, 1);
                if (p < CMAX) list[p] = seq;
            }
        }
    }
}

// exact logits on recomputed rows, scatter chosen back
__global__ void logits_fix_k(const float* __restrict__ XR, const float* __restrict__ W,
                             const float* __restrict__ bias, const int* __restrict__ list,
                             const int* __restrict__ cntp, int* __restrict__ chosen)
{
    int gtid = blockIdx.x * blockDim.x + threadIdx.x;
    int ct   = gtid >> 5;
    int lane = threadIdx.x & 31;
    int c = *cntp; if (c > CMAX) c = CMAX;
    if (ct >= c * SEQ) return;
    const float* xr = XR + (size_t)ct * DM;
    float a0 = 0, a1 = 0, a2 = 0;
    for (int j = lane; j < DM; j += 32) {
        float x = xr[j];
        a0 += x * W[j * 3 + 0];
        a1 += x * W[j * 3 + 1];
        a2 += x * W[j * 3 + 2];
    }
#pragma unroll
    for (int o = 16; o > 0; o >>= 1) {
        a0 += __shfl_xor_sync(0xffffffffu, a0, o);
        a1 += __shfl_xor_sync(0xffffffffu, a1, o);
        a2 += __shfl_xor_sync(0xffffffffu, a2, o);
    }
    if (lane == 0) {
        a0 += bias[0]; a1 += bias[1]; a2 += bias[2];
        int idx = 0; float best = a0;
        if (a1 > best) { best = a1; idx = 1; }
        if (a2 > best) { best = a2; idx = 2; }
        int orig = list[ct >> 5] * SEQ + (ct & 31);
        chosen[orig] = idx;
    }
}

// ---------------- small utility kernels ----------------
__global__ void zero_k(int* __restrict__ flag, int* __restrict__ cnt) {
    int i = blockIdx.x * 256 + threadIdx.x;
    if (i < NSEQ) flag[i] = 0;
    if (i == 0) cnt[0] = 0;
}

__global__ void gather_k(const float* __restrict__ x, const int* __restrict__ list,
                         const int* __restrict__ cntp, float* __restrict__ XR) {
    int s = blockIdx.x;
    int c = *cntp; if (c > CMAX) c = CMAX;
    if (s >= c) return;
    int orig = list[s];
    const float4* src = (const float4*)(x + (size_t)orig * SEQ * DM);
    float4* dst = (float4*)(XR + (size_t)s * SEQ * DM);
    for (int i = threadIdx.x; i < SEQ * DM / 4; i += 256) dst[i] = src[i];
}

__global__ void maskmul_k(const float4* __restrict__ x, const float* __restrict__ mask,
                          float4* __restrict__ out, int n4) {
    int i = blockIdx.x * 256 + threadIdx.x;
    if (i < n4) {
        float m = mask[i >> 8];
        float4 v = x[i];
        v.x *= m; v.y *= m; v.z *= m; v.w *= m;
        out[i] = v;
    }
}

__global__ void msum_k(const float* __restrict__ mask, float* __restrict__ ms) {
    int b = blockIdx.x, lane = threadIdx.x;
    float m = mask[b * SEQ + lane];
#pragma unroll
    for (int o = 16; o > 0; o >>= 1) m += __shfl_xor_sync(0xffffffffu, m, o);
    if (lane == 0) ms[b] = m;
}

__global__ void compress_k(const int* __restrict__ chosen, const float* __restrict__ mask,
                           float* __restrict__ comp) {
    int b = blockIdx.x, lane = threadIdx.x;
    float c = (float)chosen[b * SEQ + lane] / 3.0f;
    float m = mask[b * SEQ + lane];
    float num = c * m, den = m;
#pragma unroll
    for (int o = 16; o > 0; o >>= 1) {
        num += __shfl_xor_sync(0xffffffffu, num, o);
        den += __shfl_xor_sync(0xffffffffu, den, o);
    }
    if (lane == 0) comp[b] = num / den;
}

// ---------------- final assembly ----------------
__global__ __launch_bounds__(256) void assemble_k(
    const float* __restrict__ x, const float* __restrict__ mask,
    const int* __restrict__ chosen, const float* __restrict__ msum,
    const float* __restrict__ P1, const float* __restrict__ P2,
    const float* __restrict__ emb,
    float* __restrict__ out, float* __restrict__ masks_out)
{
    const int r = blockIdx.x;
    const int b = r >> 5, pos = r & 31;
    const int tid = threadIdx.x;
    const int c = chosen[r];
    const float ms = msum[b];

    float4* o4 = (float4*)(out + (size_t)r * DM);
    float maskv;

    if (c == 0) {
        o4[tid] = ((const float4*)(x + (size_t)r * DM))[tid];
        maskv = mask[r];
    } else if (c == 1) {
        float nm = ((float)pos < ms * 0.5f) ? 1.0f : 0.0f;
        float4 e = ((const float4*)emb)[tid];
        float4 pv = make_float4(0, 0, 0, 0);
        if (pos < 16) pv = ((const float4*)(P1 + (size_t)(b * 16 + pos) * DM))[tid];
        o4[tid] = make_float4(pv.x * nm + e.x, pv.y * nm + e.y,
                              pv.z * nm + e.z, pv.w * nm + e.w);
        maskv = nm;
    } else {
        float nm = ((float)pos < ms * 0.25f) ? 1.0f : 0.0f;
        float4 e = ((const float4*)(emb + DM))[tid];
        float4 pv = make_float4(0, 0, 0, 0);
        if (pos < 8) pv = ((const float4*)(P2 + (size_t)(b * 8 + pos) * DM))[tid];
        o4[tid] = make_float4(pv.x * nm + e.x, pv.y * nm + e.y,
                              pv.z * nm + e.z, pv.w * nm + e.w);
        maskv = nm;
    }
    if (tid == 0) masks_out[r] = maskv;
}

// ---------------- launch ----------------
extern "C" void kernel_launch(void* const* d_in, const int* in_sizes, int n_in,
                              void* d_out, int out_size)
{
    const float* x     = (const float*)d_in[0];
    const float* mask  = (const float*)d_in[1];
    const float* ln1_w = (const float*)d_in[2];
    const float* ln1_b = (const float*)d_in[3];
    const float* wqkv  = (const float*)d_in[4];
    const float* bqkv  = (const float*)d_in[5];
    const float* wo    = (const float*)d_in[6];
    const float* bo    = (const float*)d_in[7];
    const float* ln2_w = (const float*)d_in[8];
    const float* ln2_b = (const float*)d_in[9];
    const float* w1    = (const float*)d_in[10];
    const float* b1    = (const float*)d_in[11];
    const float* w2    = (const float*)d_in[12];
    const float* b2    = (const float*)d_in[13];
    const float* rfw   = (const float*)d_in[14];
    const float* rfb   = (const float*)d_in[15];
    const float* p2w   = (const float*)d_in[16];
    const float* p2b   = (const float*)d_in[17];
    const float* p4w   = (const float*)d_in[18];
    const float* p4b   = (const float*)d_in[19];
    const float* femb  = (const float*)d_in[20];

    float *X, *H, *QKV, *MLP, *P1, *P2, *MS;
    float *XR, *HR, *QKVR, *MLPR;
    int *CH, *FLAG, *LIST, *CNT;
    __nv_bfloat16 *qkvB, *woB, *w1B, *w2B, *p2B, *p4B;
    cudaGetSymbolAddress((void**)&X,    g_X);
    cudaGetSymbolAddress((void**)&H,    g_H);
    cudaGetSymbolAddress((void**)&QKV,  g_QKV);
    cudaGetSymbolAddress((void**)&MLP,  g_MLP);
    cudaGetSymbolAddress((void**)&P1,   g_P1);
    cudaGetSymbolAddress((void**)&P2,   g_P2);
    cudaGetSymbolAddress((void**)&MS,   g_MS);
    cudaGetSymbolAddress((void**)&CH,   g_CH);
    cudaGetSymbolAddress((void**)&FLAG, g_FLAG);
    cudaGetSymbolAddress((void**)&LIST, g_LIST);
    cudaGetSymbolAddress((void**)&CNT,  g_CNT);
    cudaGetSymbolAddress((void**)&XR,   g_XR);
    cudaGetSymbolAddress((void**)&HR,   g_HR);
    cudaGetSymbolAddress((void**)&QKVR, g_QKVR);
    cudaGetSymbolAddress((void**)&MLPR, g_MLPR);
    cudaGetSymbolAddress((void**)&qkvB, g_qkvB);
    cudaGetSymbolAddress((void**)&woB,  g_woB);
    cudaGetSymbolAddress((void**)&w1B,  g_w1B);
    cudaGetSymbolAddress((void**)&w2B,  g_w2B);
    cudaGetSymbolAddress((void**)&p2B,  g_p2B);
    cudaGetSymbolAddress((void**)&p4B,  g_p4B);

    cudaFuncSetAttribute(tgemm_k<0>, cudaFuncAttributeMaxDynamicSharedMemorySize, TG_SMEM);
    cudaFuncSetAttribute(tgemm_k<1>, cudaFuncAttributeMaxDynamicSharedMemorySize, TG_SMEM);
    cudaFuncSetAttribute(tgemm_k<2>, cudaFuncAttributeMaxDynamicSharedMemorySize, TG_SMEM);

    const size_t SQKV = (size_t)3072 * 1024, SWO = (size_t)1024 * 1024;
    const size_t SW1  = (size_t)4096 * 1024, SW2 = (size_t)1024 * 4096;
    const size_t SP2  = (size_t)1024 * 2048, SP4 = (size_t)1024 * 4096;

    for (int l = 0; l < 2; l++) {
        bsplit_k<<<(int)(SQKV / 512), 256>>>(
            wqkv + l * SQKV, qkvB + (3 * l) * SQKV, qkvB + (3 * l + 1) * SQKV,
            qkvB + (3 * l + 2) * SQKV, 1024, 3072);
        bsplit_k<<<(int)(SWO / 512), 256>>>(
            wo + l * SWO, woB + (3 * l) * SWO, woB + (3 * l + 1) * SWO,
            woB + (3 * l + 2) * SWO, 1024, 1024);
        bsplit_k<<<(int)(SW1 / 512), 256>>>(
            w1 + l * SW1, w1B + (3 * l) * SW1, w1B + (3 * l + 1) * SW1,
            w1B + (3 * l + 2) * SW1, 1024, 4096);
        bsplit_k<<<(int)(SW2 / 512), 256>>>(
            w2 + l * SW2, w2B + (3 * l) * SW2, w2B + (3 * l + 1) * SW2,
            w2B + (3 * l + 2) * SW2, 4096, 1024);
    }
    bsplit_k<<<(int)(SP2 / 512), 256>>>(p2w, p2B, p2B + SP2, p2B + 2 * SP2, 2048, 1024);
    bsplit_k<<<(int)(SP4 / 512), 256>>>(p4w, p4B, p4B + SP4, p4B + 2 * SP4, 4096, 1024);

    zero_k<<<NSEQ / 256, 256>>>(FLAG, CNT);

    const int n4 = TOK * DM / 4;

    // ---- phase 1: fast bf16x6 router ----
    for (int l = 0; l < 2; l++) {
        const float* Xin = (l == 0) ? x : X;
        ln_k<<<TOK, 256>>>(Xin, ln1_w + l * DM, ln1_b + l * DM, H, nullptr);
        tgemm_k<0><<<dim3(3072 / 128, TOK / 128), 256, TG_SMEM>>>(
            H, qkvB + (3 * l) * SQKV, qkvB + (3 * l + 1) * SQKV, qkvB + (3 * l + 2) * SQKV,
            bqkv + l * 3072, nullptr, QKV, TOK, 3072, 1024);
        attn_k<<<NSEQ * NH, 256>>>(QKV, mask, H, nullptr, nullptr);
        tgemm_k<2><<<dim3(DM / 128, TOK / 128), 256, TG_SMEM>>>(
            H, woB + (3 * l) * SWO, woB + (3 * l + 1) * SWO, woB + (3 * l + 2) * SWO,
            bo + l * DM, Xin, X, TOK, DM, 1024);
        ln_k<<<TOK, 256>>>(X, ln2_w + l * DM, ln2_b + l * DM, H, nullptr);
        tgemm_k<1><<<dim3(4096 / 128, TOK / 128), 256, TG_SMEM>>>(
            H, w1B + (3 * l) * SW1, w1B + (3 * l + 1) * SW1,
            w1B + (3 * l + 2) * SW1, b1 + l * 4096, nullptr, MLP, TOK, 4096, 1024);
        tgemm_k<2><<<dim3(DM / 128, TOK / 128), 256, TG_SMEM>>>(
            MLP, w2B + (3 * l) * SW2, w2B + (3 * l + 1) * SW2, w2B + (3 * l + 2) * SW2,
            b2 + l * DM, X, X, TOK, DM, 4096);
    }

    logits_margin_k<<<TOK / 8, 256>>>(X, rfw, rfb, CH, FLAG, LIST, CNT);

    // ---- phase 2: exact FFMA recompute of flagged sequences ----
    gather_k<<<CMAX, 256>>>(x, LIST, CNT, XR);
    const int MR = CMAX * SEQ;   // 8192
    for (int l = 0; l < 2; l++) {
        ln_k<<<MR, 256>>>(XR, ln1_w + l * DM, ln1_b + l * DM, HR, CNT);
        fgemm_k<0><<<dim3(3072 / 128, MR / 128), 256>>>(
            HR, wqkv + l * SQKV, bqkv + l * 3072, nullptr, QKVR, MR, 3072, 1024, CNT);
        attn_k<<<CMAX * NH, 256>>>(QKVR, mask, HR, LIST, CNT);
        fgemm_k<2><<<dim3(DM / 128, MR / 128), 256>>>(
            HR, wo + l * SWO, bo + l * DM, XR, XR, MR, DM, 1024, CNT);
        ln_k<<<MR, 256>>>(XR, ln2_w + l * DM, ln2_b + l * DM, HR, CNT);
        fgemm_k<1><<<dim3(4096 / 128, MR / 128), 256>>>(
            HR, w1 + l * SW1, b1 + l * 4096, nullptr, MLPR, MR, 4096, 1024, CNT);
        fgemm_k<2><<<dim3(DM / 128, MR / 128), 256>>>(
            MLPR, w2 + l * SW2, b2 + l * DM, XR, XR, MR, DM, 4096, CNT);
    }
    logits_fix_k<<<MR / 8, 256>>>(XR, rfw, rfb, LIST, CNT, CH);

    // ---- pools + assembly ----
    maskmul_k<<<n4 / 256, 256>>>((const float4*)x, mask, (float4*)QKV, n4);
    tgemm_k<0><<<dim3(DM / 128, 16384 / 128), 256, TG_SMEM>>>(
        QKV, p2B, p2B + SP2, p2B + 2 * SP2, p2b, nullptr, P1, 16384, DM, 2048);
    tgemm_k<0><<<dim3(DM / 128, 8192 / 128), 256, TG_SMEM>>>(
        QKV, p4B, p4B + SP4, p4B + 2 * SP4, p4b, nullptr, P2, 8192, DM, 4096);

    msum_k<<<NSEQ, 32>>>(mask, MS);

    float* out = (float*)d_out;
    assemble_k<<<TOK, 256>>>(x, mask, CH, MS, P1, P2, femb, out, out + (size_t)TOK * DM);
    compress_k<<<NSEQ, 32>>>(CH, mask, out + (size_t)TOK * DM + TOK);
}

// round 8
// speedup vs baseline: 2.2946x; 1.4866x over previous
#include <cuda_runtime.h>
#include <cuda_bf16.h>
#include <math.h>
#include <stdint.h>

#define TOK   32768
#define DM    1024
#define NSEQ  1024
#define SEQ   32
#define NH    16
#define HD    64
#define CMAX  256          // max sequences recomputed exactly
#define TAU   2e-3f        // argmax margin threshold

// ---------------- scratch ----------------
static __device__ float g_X  [TOK * DM];
static __device__ float g_H  [TOK * DM];
static __device__ float g_QKV[TOK * 3 * DM];
static __device__ float g_MLP[TOK * 4 * DM];
static __device__ float g_P1 [NSEQ * 16 * DM];
static __device__ float g_P2 [NSEQ * 8  * DM];
static __device__ int   g_CH [TOK];
static __device__ float g_MS [NSEQ];

// selective exact-recompute state
static __device__ int   g_FLAG[NSEQ];
static __device__ int   g_LIST[CMAX];
static __device__ int   g_CNT [1];
static __device__ float g_XR  [CMAX * SEQ * DM];
static __device__ float g_HR  [CMAX * SEQ * DM];
static __device__ float g_QKVR[CMAX * SEQ * 3 * DM];
static __device__ float g_MLPR[CMAX * SEQ * 4 * DM];

// fragment-major bf16 weight planes [layer][plane h/m]
static __device__ __nv_bfloat16 g_qkvB[2][2][3072 * 1024];
static __device__ __nv_bfloat16 g_woB [2][2][1024 * 1024];
static __device__ __nv_bfloat16 g_w1B [2][2][4096 * 1024];
static __device__ __nv_bfloat16 g_w2B [2][2][1024 * 4096];
static __device__ __nv_bfloat16 g_p2B [2][1024 * 2048];
static __device__ __nv_bfloat16 g_p4B [2][1024 * 4096];

// ---------------- helpers ----------------
__device__ __forceinline__ float gelu_tanh(float x) {
    const float c = 0.7978845608028654f;
    float x3 = x * x * x;
    return 0.5f * x * (1.0f + tanhf(c * (x + 0.044715f * x3)));
}
__device__ __forceinline__ uint32_t pack2(__nv_bfloat16 a, __nv_bfloat16 b) {
    __nv_bfloat162 t; t.x = a; t.y = b;
    return *reinterpret_cast<uint32_t*>(&t);
}
__device__ __forceinline__ uint32_t smem_u32(const void* p) {
    uint32_t a;
    asm("{ .reg .u64 t; cvta.to.shared.u64 t, %1; cvt.u32.u64 %0, t; }" : "=r"(a) : "l"(p));
    return a;
}
__device__ __forceinline__ void cp_async16(uint32_t saddr, const void* g) {
    asm volatile("cp.async.ca.shared.global [%0], [%1], 16;" :: "r"(saddr), "l"(g));
}
#define CP_COMMIT() asm volatile("cp.async.commit_group;" ::: "memory")
#define CP_WAIT0()  asm volatile("cp.async.wait_group 0;" ::: "memory")

#define MMA_BF16(cd, a, b) \
    asm volatile("mma.sync.aligned.m16n8k16.row.col.f32.bf16.bf16.f32 " \
        "{%0,%1,%2,%3}, {%4,%5,%6,%7}, {%8,%9}, {%0,%1,%2,%3};" \
        : "+f"((cd)[0]), "+f"((cd)[1]), "+f"((cd)[2]), "+f"((cd)[3]) \
        : "r"((a).x), "r"((a).y), "r"((a).z), "r"((a).w), \
          "r"((b).x), "r"((b).y))

// ============ weight preprocess: W[K][N] -> fragment-major bf16 h/m =======
__global__ __launch_bounds__(256) void bsplit_k(
    const float* __restrict__ W,
    __nv_bfloat16* __restrict__ Th, __nv_bfloat16* __restrict__ Tm,
    int K, int N)
{
    int idx = blockIdx.x * 256 + threadIdx.x;   // over K*N/2
    int n = idx % N;
    int k = (idx / N) * 2;
    float v0 = W[(size_t)k * N + n];
    float v1 = W[(size_t)(k + 1) * N + n];

    __nv_bfloat16 h0 = __float2bfloat16(v0); float r0 = v0 - __bfloat162float(h0);
    __nv_bfloat16 m0 = __float2bfloat16(r0);
    __nv_bfloat16 h1 = __float2bfloat16(v1); float r1 = v1 - __bfloat162float(h1);
    __nv_bfloat16 m1 = __float2bfloat16(r1);

    size_t t = (size_t)(n >> 3) * (K >> 4) + (k >> 4);
    int lane = (n & 7) * 4 + ((k & 7) >> 1);
    int reg  = (k & 15) >> 3;
    size_t o = t * 64 + lane * 2 + reg;
    ((uint32_t*)Th)[o] = pack2(h0, h1);
    ((uint32_t*)Tm)[o] = pack2(m0, m1);
}

// ============ bf16x3 tensor-core GEMM (fast path) ==========================
// Terms: hh, hm, mh (residual ~3*2^-18 per product, random sign).
#define BK     32
#define SA_PL  2048
#define SB_OFF 4096
#define SB_PL  2048
#define STG    8192
#define TG_SMEM (2 * STG * 4)

__device__ __forceinline__ void stsA(uint32_t* smu, uint32_t base, int tid,
                                     const float4* av) {
#pragma unroll
    for (int p = 0; p < 4; p++) {
        int id = tid + p * 256;
        int row = id >> 3, c4 = (id & 7) << 2;
        int mt = row >> 4, r = row & 15;
        int kt = c4 >> 4;
        int reg = (r >> 3) | (((c4 >> 3) & 1) << 1);
        int lane0 = (r & 7) * 4 + ((c4 & 7) >> 1);
        uint32_t tbase = base + (mt * 2 + kt) * 128;
        float v[4] = {av[p].x, av[p].y, av[p].z, av[p].w};
#pragma unroll
        for (int q = 0; q < 2; q++) {
            float e0 = v[2 * q], e1 = v[2 * q + 1];
            __nv_bfloat16 h0 = __float2bfloat16(e0);
            __nv_bfloat16 m0 = __float2bfloat16(e0 - __bfloat162float(h0));
            __nv_bfloat16 h1 = __float2bfloat16(e1);
            __nv_bfloat16 m1 = __float2bfloat16(e1 - __bfloat162float(h1));
            uint32_t off = (uint32_t)((lane0 + q) * 4 + reg);
            smu[tbase + off]         = pack2(h0, h1);
            smu[tbase + SA_PL + off] = pack2(m0, m1);
        }
    }
}

template<int MODE>
__global__ __launch_bounds__(256, 1) void tgemm_k(
    const float* __restrict__ A,
    const __nv_bfloat16* __restrict__ Bhg, const __nv_bfloat16* __restrict__ Bmg,
    const float* __restrict__ bias, const float* __restrict__ res,
    float* __restrict__ C, int M, int N, int K)
{
    extern __shared__ float sm[];
    uint32_t* smu = (uint32_t*)sm;
    const uint32_t smb = smem_u32(sm);

    const int tid = threadIdx.x;
    const int wid = tid >> 5, lane = tid & 31;
    const int wm = wid & 1, wn = wid >> 1;
    const int m0 = blockIdx.y * 128, n0 = blockIdx.x * 128;
    const int K16 = K >> 4;

    float acc[4][4][4];
#pragma unroll
    for (int i = 0; i < 4; i++)
#pragma unroll
        for (int j = 0; j < 4; j++)
#pragma unroll
            for (int q = 0; q < 4; q++) acc[i][j][q] = 0.0f;

    const int nst = K / BK;
    float4 aval[4];

#pragma unroll
    for (int p = 0; p < 4; p++) {
        int id = tid + p * 256;
        int row = id >> 3, c4 = (id & 7) << 2;
        aval[p] = *(const float4*)(A + (size_t)(m0 + row) * K + c4);
    }
#pragma unroll
    for (int p = 0; p < 4; p++) {
        int id = tid + p * 256;
        int plane = id >> 9, rem = id & 511;
        int tile = rem >> 4, f = rem & 15;
        int ntl = tile >> 1, ktl = tile & 1;
        const __nv_bfloat16* src = plane ? Bmg : Bhg;
        size_t gt = (size_t)((n0 >> 3) + ntl) * K16 + ktl;
        cp_async16(smb + (uint32_t)(SB_OFF + plane * SB_PL + tile * 64 + f * 4) * 4,
                   (const char*)src + gt * 256 + f * 16);
    }
    CP_COMMIT();
    stsA(smu, 0, tid, aval);
    CP_WAIT0();
    __syncthreads();

    for (int st = 0; st < nst; st++) {
        const int buf = st & 1;
        const bool more = (st + 1) < nst;
        if (more) {
            const int k0n = (st + 1) * BK;
#pragma unroll
            for (int p = 0; p < 4; p++) {
                int id = tid + p * 256;
                int row = id >> 3, c4 = (id & 7) << 2;
                aval[p] = *(const float4*)(A + (size_t)(m0 + row) * K + k0n + c4);
            }
            const uint32_t nbase = (uint32_t)((buf ^ 1) * STG);
#pragma unroll
            for (int p = 0; p < 4; p++) {
                int id = tid + p * 256;
                int plane = id >> 9, rem = id & 511;
                int tile = rem >> 4, f = rem & 15;
                int ntl = tile >> 1, ktl = tile & 1;
                const __nv_bfloat16* src = plane ? Bmg : Bhg;
                size_t gt = (size_t)((n0 >> 3) + ntl) * K16 + (k0n >> 4) + ktl;
                cp_async16(smb + (nbase + SB_OFF + plane * SB_PL + tile * 64 + f * 4) * 4,
                           (const char*)src + gt * 256 + f * 16);
            }
            CP_COMMIT();
        }

        const uint32_t ab = (uint32_t)(buf * STG);
        const uint32_t bb = ab + SB_OFF;
#pragma unroll
        for (int kt = 0; kt < 2; kt++) {
            uint4 Ah[4], Am[4];
            uint2 Bh[4], Bm[4];
#pragma unroll
            for (int mt = 0; mt < 4; mt++)
                Ah[mt] = *((const uint4*)(smu + ab + ((wm * 4 + mt) * 2 + kt) * 128) + lane);
#pragma unroll
            for (int nt = 0; nt < 4; nt++)
                Bh[nt] = *((const uint2*)(smu + bb + ((wn * 4 + nt) * 2 + kt) * 64) + lane);
#pragma unroll
            for (int mt = 0; mt < 4; mt++)
#pragma unroll
                for (int nt = 0; nt < 4; nt++) MMA_BF16(acc[mt][nt], Ah[mt], Bh[nt]);

#pragma unroll
            for (int nt = 0; nt < 4; nt++)
                Bm[nt] = *((const uint2*)(smu + bb + SB_PL + ((wn * 4 + nt) * 2 + kt) * 64) + lane);
#pragma unroll
            for (int mt = 0; mt < 4; mt++)
#pragma unroll
                for (int nt = 0; nt < 4; nt++) MMA_BF16(acc[mt][nt], Ah[mt], Bm[nt]);

#pragma unroll
            for (int mt = 0; mt < 4; mt++)
                Am[mt] = *((const uint4*)(smu + ab + SA_PL + ((wm * 4 + mt) * 2 + kt) * 128) + lane);
#pragma unroll
            for (int mt = 0; mt < 4; mt++)
#pragma unroll
                for (int nt = 0; nt < 4; nt++) MMA_BF16(acc[mt][nt], Am[mt], Bh[nt]);
        }

        if (more) stsA(smu, (uint32_t)((buf ^ 1) * STG), tid, aval);
        CP_WAIT0();
        __syncthreads();
    }

    const int r0 = lane >> 2, cc = (lane & 3) * 2;
#pragma unroll
    for (int mt = 0; mt < 4; mt++) {
#pragma unroll
        for (int nt = 0; nt < 4; nt++) {
            int gm = m0 + wm * 64 + mt * 16 + r0;
            int gn = n0 + wn * 32 + nt * 8 + cc;
            float b0 = bias[gn], b1 = bias[gn + 1];
            float v0 = acc[mt][nt][0] + b0, v1 = acc[mt][nt][1] + b1;
            float v2 = acc[mt][nt][2] + b0, v3 = acc[mt][nt][3] + b1;
            size_t o0 = (size_t)gm * N + gn;
            size_t o1 = (size_t)(gm + 8) * N + gn;
            if (MODE == 1) {
                v0 = gelu_tanh(v0); v1 = gelu_tanh(v1);
                v2 = gelu_tanh(v2); v3 = gelu_tanh(v3);
            }
            if (MODE == 2) {
                v0 += res[o0]; v1 += res[o0 + 1];
                v2 += res[o1]; v3 += res[o1 + 1];
            }
            *(float2*)(C + o0) = make_float2(v0, v1);
            *(float2*)(C + o1) = make_float2(v2, v3);
        }
    }
}

// ============ exact FFMA SGEMM (verbatim R1 semantics) + early exit ========
template<int MODE>
__global__ __launch_bounds__(256) void fgemm_k(
    const float* __restrict__ A, const float* __restrict__ B,
    const float* __restrict__ bias, const float* __restrict__ res,
    float* __restrict__ C, int M, int N, int K, const int* __restrict__ cntp)
{
    const int m0 = blockIdx.y * 128;
    if (cntp) {
        int c = *cntp; if (c > CMAX) c = CMAX;
        if (m0 >= c * SEQ) return;
    }
    __shared__ float As[16][128];
    __shared__ float Bs[16][128];

    const int tid = threadIdx.x;
    const int n0 = blockIdx.x * 128;

    const int tx = tid & 15;
    const int ty = tid >> 4;
    const int row0 = ty * 8;
    const int col0 = tx * 8;

    const int aRow = tid >> 2;
    const int aCol = (tid & 3) << 2;
    const int bRow = tid >> 5;
    const int bCol = (tid & 31) << 2;

    float acc[8][8];
#pragma unroll
    for (int i = 0; i < 8; i++)
#pragma unroll
        for (int j = 0; j < 8; j++) acc[i][j] = 0.0f;

    const float* Ag = A + (size_t)m0 * K;

    for (int k0 = 0; k0 < K; k0 += 16) {
        float4 a0 = *(const float4*)(Ag + (size_t)aRow        * K + k0 + aCol);
        float4 a1 = *(const float4*)(Ag + (size_t)(aRow + 64) * K + k0 + aCol);
        As[aCol + 0][aRow] = a0.x; As[aCol + 1][aRow] = a0.y;
        As[aCol + 2][aRow] = a0.z; As[aCol + 3][aRow] = a0.w;
        As[aCol + 0][aRow + 64] = a1.x; As[aCol + 1][aRow + 64] = a1.y;
        As[aCol + 2][aRow + 64] = a1.z; As[aCol + 3][aRow + 64] = a1.w;

        float4 b0 = *(const float4*)(B + (size_t)(k0 + bRow)     * N + n0 + bCol);
        float4 b1 = *(const float4*)(B + (size_t)(k0 + bRow + 8) * N + n0 + bCol);
        *(float4*)&Bs[bRow][bCol]     = b0;
        *(float4*)&Bs[bRow + 8][bCol] = b1;

        __syncthreads();

#pragma unroll
        for (int kk = 0; kk < 16; kk++) {
            float a[8], b[8];
            *(float4*)(a)     = *(const float4*)&As[kk][row0];
            *(float4*)(a + 4) = *(const float4*)&As[kk][row0 + 4];
            *(float4*)(b)     = *(const float4*)&Bs[kk][col0];
            *(float4*)(b + 4) = *(const float4*)&Bs[kk][col0 + 4];
#pragma unroll
            for (int i = 0; i < 8; i++)
#pragma unroll
                for (int j = 0; j < 8; j++)
                    acc[i][j] += a[i] * b[j];
        }
        __syncthreads();
    }

    float bv[8];
#pragma unroll
    for (int j = 0; j < 8; j++) bv[j] = bias[n0 + col0 + j];

#pragma unroll
    for (int i = 0; i < 8; i++) {
        size_t off = (size_t)(m0 + row0 + i) * N + n0 + col0;
        float v[8];
#pragma unroll
        for (int j = 0; j < 8; j++) {
            float t = acc[i][j] + bv[j];
            if (MODE == 1) t = gelu_tanh(t);
            if (MODE == 2) t += res[off + j];
            v[j] = t;
        }
        *(float4*)(C + off)     = make_float4(v[0], v[1], v[2], v[3]);
        *(float4*)(C + off + 4) = make_float4(v[4], v[5], v[6], v[7]);
    }
}

// ---------------- LayerNorm (shared by fast + exact paths) ----------------
__global__ __launch_bounds__(256) void ln_k(
    const float* __restrict__ X, const float* __restrict__ w,
    const float* __restrict__ b, float* __restrict__ out,
    const int* __restrict__ cntp)
{
    const int row = blockIdx.x;
    if (cntp) {
        int c = *cntp; if (c > CMAX) c = CMAX;
        if (row >= c * SEQ) return;
    }
    const int tid = threadIdx.x;
    const int lane = tid & 31, wid = tid >> 5;
    __shared__ float red[8];

    float4 xv = ((const float4*)(X + (size_t)row * DM))[tid];
    float s = xv.x + xv.y + xv.z + xv.w;
#pragma unroll
    for (int o = 16; o > 0; o >>= 1) s += __shfl_xor_sync(0xffffffffu, s, o);
    if (lane == 0) red[wid] = s;
    __syncthreads();
    s = red[0] + red[1] + red[2] + red[3] + red[4] + red[5] + red[6] + red[7];
    float mean = s * (1.0f / 1024.0f);

    float dx = xv.x - mean, dy = xv.y - mean, dz = xv.z - mean, dw = xv.w - mean;
    float sq = dx * dx + dy * dy + dz * dz + dw * dw;
#pragma unroll
    for (int o = 16; o > 0; o >>= 1) sq += __shfl_xor_sync(0xffffffffu, sq, o);
    __syncthreads();
    if (lane == 0) red[wid] = sq;
    __syncthreads();
    sq = red[0] + red[1] + red[2] + red[3] + red[4] + red[5] + red[6] + red[7];
    float rstd = rsqrtf(sq * (1.0f / 1024.0f) + 1e-5f);

    float4 wv = ((const float4*)w)[tid];
    float4 bv = ((const float4*)b)[tid];
    float4 o4;
    o4.x = dx * rstd * wv.x + bv.x;
    o4.y = dy * rstd * wv.y + bv.y;
    o4.z = dz * rstd * wv.z + bv.z;
    o4.w = dw * rstd * wv.w + bv.w;
    ((float4*)(out + (size_t)row * DM))[tid] = o4;
}

// ---------------- attention (fast: seqlist == nullptr) ----------------
__global__ __launch_bounds__(256) void attn_k(
    const float* __restrict__ QKV, const float* __restrict__ mask,
    float* __restrict__ O, const int* __restrict__ seqlist,
    const int* __restrict__ cntp)
{
    __shared__ float qs[SEQ * HD];
    __shared__ float ks[SEQ * (HD + 1)];
    __shared__ float vs[SEQ * (HD + 1)];
    __shared__ float sc[SEQ * SEQ];

    const int bseq = blockIdx.x >> 4;
    const int h    = blockIdx.x & 15;
    const int tid  = threadIdx.x;

    int mseq = bseq;
    if (cntp) {
        int c = *cntp; if (c > CMAX) c = CMAX;
        if (bseq >= c) return;
        mseq = seqlist[bseq];
    }

    const float* base = QKV + (size_t)(bseq * SEQ) * 3072 + h * HD;
    for (int i = tid; i < SEQ * HD; i += 256) {
        int t = i >> 6, d = i & 63;
        qs[t * HD + d]       = base[(size_t)t * 3072 + d];
        ks[t * (HD + 1) + d] = base[(size_t)t * 3072 + 1024 + d];
        vs[t * (HD + 1) + d] = base[(size_t)t * 3072 + 2048 + d];
    }
    __syncthreads();

    for (int i = tid; i < SEQ * SEQ; i += 256) {
        int qi = i >> 5, ki = i & 31;
        float s = 0.0f;
#pragma unroll
        for (int d = 0; d < HD; d++) s += qs[qi * HD + d] * ks[ki * (HD + 1) + d];
        float mb = (mask[mseq * SEQ + ki] > 0.0f) ? 0.0f : -1e9f;
        sc[i] = s * 0.125f + mb;
    }
    __syncthreads();

    {
        int wid = tid >> 5, lane = tid & 31;
        for (int r = wid; r < SEQ; r += 8) {
            float v = sc[r * SEQ + lane];
            float mx = v;
#pragma unroll
            for (int o = 16; o > 0; o >>= 1) mx = fmaxf(mx, __shfl_xor_sync(0xffffffffu, mx, o));
            float e = expf(v - mx);
            float su = e;
#pragma unroll
            for (int o = 16; o > 0; o >>= 1) su += __shfl_xor_sync(0xffffffffu, su, o);
            sc[r * SEQ + lane] = e / su;
        }
    }
    __syncthreads();

    for (int i = tid; i < SEQ * HD; i += 256) {
        int t = i >> 6, d = i & 63;
        float o = 0.0f;
#pragma unroll
        for (int k = 0; k < SEQ; k++) o += sc[t * SEQ + k] * vs[k * (HD + 1) + d];
        O[(size_t)(bseq * SEQ + t) * DM + h * HD + d] = o;
    }
}

// ---------------- logits + argmax + margin flagging ----------------
__global__ void logits_margin_k(const float* __restrict__ X, const float* __restrict__ W,
                                const float* __restrict__ bias, int* __restrict__ chosen,
                                int* __restrict__ flag, int* __restrict__ list,
                                int* __restrict__ cnt)
{
    int gtid = blockIdx.x * blockDim.x + threadIdx.x;
    int row  = gtid >> 5;
    int lane = threadIdx.x & 31;
    if (row >= TOK) return;
    const float* xr = X + (size_t)row * DM;
    float a0 = 0, a1 = 0, a2 = 0;
    for (int j = lane; j < DM; j += 32) {
        float x = xr[j];
        a0 += x * W[j * 3 + 0];
        a1 += x * W[j * 3 + 1];
        a2 += x * W[j * 3 + 2];
    }
#pragma unroll
    for (int o = 16; o > 0; o >>= 1) {
        a0 += __shfl_xor_sync(0xffffffffu, a0, o);
        a1 += __shfl_xor_sync(0xffffffffu, a1, o);
        a2 += __shfl_xor_sync(0xffffffffu, a2, o);
    }
    if (lane == 0) {
        a0 += bias[0]; a1 += bias[1]; a2 += bias[2];
        int idx = 0; float best = a0;
        if (a1 > best) { best = a1; idx = 1; }
        if (a2 > best) { best = a2; idx = 2; }
        chosen[row] = idx;
        float s2 = -3.4e38f;
        if (idx != 0 && a0 > s2) s2 = a0;
        if (idx != 1 && a1 > s2) s2 = a1;
        if (idx != 2 && a2 > s2) s2 = a2;
        if (best - s2 < TAU) {
            int seq = row >> 5;
            if (atomicExch(&flag[seq], 1) == 0) {
                int p = atomicAdd(cnt, 1);
                if (p < CMAX) list[p] = seq;
            }
        }
    }
}

// exact logits on recomputed rows, scatter chosen back
__global__ void logits_fix_k(const float* __restrict__ XR, const float* __restrict__ W,
                             const float* __restrict__ bias, const int* __restrict__ list,
                             const int* __restrict__ cntp, int* __restrict__ chosen)
{
    int gtid = blockIdx.x * blockDim.x + threadIdx.x;
    int ct   = gtid >> 5;
    int lane = threadIdx.x & 31;
    int c = *cntp; if (c > CMAX) c = CMAX;
    if (ct >= c * SEQ) return;
    const float* xr = XR + (size_t)ct * DM;
    float a0 = 0, a1 = 0, a2 = 0;
    for (int j = lane; j < DM; j += 32) {
        float x = xr[j];
        a0 += x * W[j * 3 + 0];
        a1 += x * W[j * 3 + 1];
        a2 += x * W[j * 3 + 2];
    }
#pragma unroll
    for (int o = 16; o > 0; o >>= 1) {
        a0 += __shfl_xor_sync(0xffffffffu, a0, o);
        a1 += __shfl_xor_sync(0xffffffffu, a1, o);
        a2 += __shfl_xor_sync(0xffffffffu, a2, o);
    }
    if (lane == 0) {
        a0 += bias[0]; a1 += bias[1]; a2 += bias[2];
        int idx = 0; float best = a0;
        if (a1 > best) { best = a1; idx = 1; }
        if (a2 > best) { best = a2; idx = 2; }
        int orig = list[ct >> 5] * SEQ + (ct & 31);
        chosen[orig] = idx;
    }
}

// ---------------- small utility kernels ----------------
__global__ void zero_k(int* __restrict__ flag, int* __restrict__ cnt) {
    int i = blockIdx.x * 256 + threadIdx.x;
    if (i < NSEQ) flag[i] = 0;
    if (i == 0) cnt[0] = 0;
}

__global__ void gather_k(const float* __restrict__ x, const int* __restrict__ list,
                         const int* __restrict__ cntp, float* __restrict__ XR) {
    int s = blockIdx.x;
    int c = *cntp; if (c > CMAX) c = CMAX;
    if (s >= c) return;
    int orig = list[s];
    const float4* src = (const float4*)(x + (size_t)orig * SEQ * DM);
    float4* dst = (float4*)(XR + (size_t)s * SEQ * DM);
    for (int i = threadIdx.x; i < SEQ * DM / 4; i += 256) dst[i] = src[i];
}

__global__ void maskmul_k(const float4* __restrict__ x, const float* __restrict__ mask,
                          float4* __restrict__ out, int n4) {
    int i = blockIdx.x * 256 + threadIdx.x;
    if (i < n4) {
        float m = mask[i >> 8];
        float4 v = x[i];
        v.x *= m; v.y *= m; v.z *= m; v.w *= m;
        out[i] = v;
    }
}

__global__ void msum_k(const float* __restrict__ mask, float* __restrict__ ms) {
    int b = blockIdx.x, lane = threadIdx.x;
    float m = mask[b * SEQ + lane];
#pragma unroll
    for (int o = 16; o > 0; o >>= 1) m += __shfl_xor_sync(0xffffffffu, m, o);
    if (lane == 0) ms[b] = m;
}

__global__ void compress_k(const int* __restrict__ chosen, const float* __restrict__ mask,
                           float* __restrict__ comp) {
    int b = blockIdx.x, lane = threadIdx.x;
    float c = (float)chosen[b * SEQ + lane] / 3.0f;
    float m = mask[b * SEQ + lane];
    float num = c * m, den = m;
#pragma unroll
    for (int o = 16; o > 0; o >>= 1) {
        num += __shfl_xor_sync(0xffffffffu, num, o);
        den += __shfl_xor_sync(0xffffffffu, den, o);
    }
    if (lane == 0) comp[b] = num / den;
}

// ---------------- final assembly ----------------
__global__ __launch_bounds__(256) void assemble_k(
    const float* __restrict__ x, const float* __restrict__ mask,
    const int* __restrict__ chosen, const float* __restrict__ msum,
    const float* __restrict__ P1, const float* __restrict__ P2,
    const float* __restrict__ emb,
    float* __restrict__ out, float* __restrict__ masks_out)
{
    const int r = blockIdx.x;
    const int b = r >> 5, pos = r & 31;
    const int tid = threadIdx.x;
    const int c = chosen[r];
    const float ms = msum[b];

    float4* o4 = (float4*)(out + (size_t)r * DM);
    float maskv;

    if (c == 0) {
        o4[tid] = ((const float4*)(x + (size_t)r * DM))[tid];
        maskv = mask[r];
    } else if (c == 1) {
        float nm = ((float)pos < ms * 0.5f) ? 1.0f : 0.0f;
        float4 e = ((const float4*)emb)[tid];
        float4 pv = make_float4(0, 0, 0, 0);
        if (pos < 16) pv = ((const float4*)(P1 + (size_t)(b * 16 + pos) * DM))[tid];
        o4[tid] = make_float4(pv.x * nm + e.x, pv.y * nm + e.y,
                              pv.z * nm + e.z, pv.w * nm + e.w);
        maskv = nm;
    } else {
        float nm = ((float)pos < ms * 0.25f) ? 1.0f : 0.0f;
        float4 e = ((const float4*)(emb + DM))[tid];
        float4 pv = make_float4(0, 0, 0, 0);
        if (pos < 8) pv = ((const float4*)(P2 + (size_t)(b * 8 + pos) * DM))[tid];
        o4[tid] = make_float4(pv.x * nm + e.x, pv.y * nm + e.y,
                              pv.z * nm + e.z, pv.w * nm + e.w);
        maskv = nm;
    }
    if (tid == 0) masks_out[r] = maskv;
}

// ---------------- launch ----------------
extern "C" void kernel_launch(void* const* d_in, const int* in_sizes, int n_in,
                              void* d_out, int out_size)
{
    const float* x     = (const float*)d_in[0];
    const float* mask  = (const float*)d_in[1];
    const float* ln1_w = (const float*)d_in[2];
    const float* ln1_b = (const float*)d_in[3];
    const float* wqkv  = (const float*)d_in[4];
    const float* bqkv  = (const float*)d_in[5];
    const float* wo    = (const float*)d_in[6];
    const float* bo    = (const float*)d_in[7];
    const float* ln2_w = (const float*)d_in[8];
    const float* ln2_b = (const float*)d_in[9];
    const float* w1    = (const float*)d_in[10];
    const float* b1    = (const float*)d_in[11];
    const float* w2    = (const float*)d_in[12];
    const float* b2    = (const float*)d_in[13];
    const float* rfw   = (const float*)d_in[14];
    const float* rfb   = (const float*)d_in[15];
    const float* p2w   = (const float*)d_in[16];
    const float* p2b   = (const float*)d_in[17];
    const float* p4w   = (const float*)d_in[18];
    const float* p4b   = (const float*)d_in[19];
    const float* femb  = (const float*)d_in[20];

    float *X, *H, *QKV, *MLP, *P1, *P2, *MS;
    float *XR, *HR, *QKVR, *MLPR;
    int *CH, *FLAG, *LIST, *CNT;
    __nv_bfloat16 *qkvB, *woB, *w1B, *w2B, *p2B, *p4B;
    cudaGetSymbolAddress((void**)&X,    g_X);
    cudaGetSymbolAddress((void**)&H,    g_H);
    cudaGetSymbolAddress((void**)&QKV,  g_QKV);
    cudaGetSymbolAddress((void**)&MLP,  g_MLP);
    cudaGetSymbolAddress((void**)&P1,   g_P1);
    cudaGetSymbolAddress((void**)&P2,   g_P2);
    cudaGetSymbolAddress((void**)&MS,   g_MS);
    cudaGetSymbolAddress((void**)&CH,   g_CH);
    cudaGetSymbolAddress((void**)&FLAG, g_FLAG);
    cudaGetSymbolAddress((void**)&LIST, g_LIST);
    cudaGetSymbolAddress((void**)&CNT,  g_CNT);
    cudaGetSymbolAddress((void**)&XR,   g_XR);
    cudaGetSymbolAddress((void**)&HR,   g_HR);
    cudaGetSymbolAddress((void**)&QKVR, g_QKVR);
    cudaGetSymbolAddress((void**)&MLPR, g_MLPR);
    cudaGetSymbolAddress((void**)&qkvB, g_qkvB);
    cudaGetSymbolAddress((void**)&woB,  g_woB);
    cudaGetSymbolAddress((void**)&w1B,  g_w1B);
    cudaGetSymbolAddress((void**)&w2B,  g_w2B);
    cudaGetSymbolAddress((void**)&p2B,  g_p2B);
    cudaGetSymbolAddress((void**)&p4B,  g_p4B);

    cudaFuncSetAttribute(tgemm_k<0>, cudaFuncAttributeMaxDynamicSharedMemorySize, TG_SMEM);
    cudaFuncSetAttribute(tgemm_k<1>, cudaFuncAttributeMaxDynamicSharedMemorySize, TG_SMEM);
    cudaFuncSetAttribute(tgemm_k<2>, cudaFuncAttributeMaxDynamicSharedMemorySize, TG_SMEM);

    const size_t SQKV = (size_t)3072 * 1024, SWO = (size_t)1024 * 1024;
    const size_t SW1  = (size_t)4096 * 1024, SW2 = (size_t)1024 * 4096;
    const size_t SP2  = (size_t)1024 * 2048, SP4 = (size_t)1024 * 4096;

    for (int l = 0; l < 2; l++) {
        bsplit_k<<<(int)(SQKV / 512), 256>>>(
            wqkv + l * SQKV, qkvB + (2 * l) * SQKV, qkvB + (2 * l + 1) * SQKV, 1024, 3072);
        bsplit_k<<<(int)(SWO / 512), 256>>>(
            wo + l * SWO, woB + (2 * l) * SWO, woB + (2 * l + 1) * SWO, 1024, 1024);
        bsplit_k<<<(int)(SW1 / 512), 256>>>(
            w1 + l * SW1, w1B + (2 * l) * SW1, w1B + (2 * l + 1) * SW1, 1024, 4096);
        bsplit_k<<<(int)(SW2 / 512), 256>>>(
            w2 + l * SW2, w2B + (2 * l) * SW2, w2B + (2 * l + 1) * SW2, 4096, 1024);
    }
    bsplit_k<<<(int)(SP2 / 512), 256>>>(p2w, p2B, p2B + SP2, 2048, 1024);
    bsplit_k<<<(int)(SP4 / 512), 256>>>(p4w, p4B, p4B + SP4, 4096, 1024);

    zero_k<<<NSEQ / 256, 256>>>(FLAG, CNT);

    const int n4 = TOK * DM / 4;

    // ---- phase 1: fast bf16x3 router ----
    for (int l = 0; l < 2; l++) {
        const float* Xin = (l == 0) ? x : X;
        ln_k<<<TOK, 256>>>(Xin, ln1_w + l * DM, ln1_b + l * DM, H, nullptr);
        tgemm_k<0><<<dim3(3072 / 128, TOK / 128), 256, TG_SMEM>>>(
            H, qkvB + (2 * l) * SQKV, qkvB + (2 * l + 1) * SQKV,
            bqkv + l * 3072, nullptr, QKV, TOK, 3072, 1024);
        attn_k<<<NSEQ * NH, 256>>>(QKV, mask, H, nullptr, nullptr);
        tgemm_k<2><<<dim3(DM / 128, TOK / 128), 256, TG_SMEM>>>(
            H, woB + (2 * l) * SWO, woB + (2 * l + 1) * SWO,
            bo + l * DM, Xin, X, TOK, DM, 1024);
        ln_k<<<TOK, 256>>>(X, ln2_w + l * DM, ln2_b + l * DM, H, nullptr);
        tgemm_k<1><<<dim3(4096 / 128, TOK / 128), 256, TG_SMEM>>>(
            H, w1B + (2 * l) * SW1, w1B + (2 * l + 1) * SW1,
            b1 + l * 4096, nullptr, MLP, TOK, 4096, 1024);
        tgemm_k<2><<<dim3(DM / 128, TOK / 128), 256, TG_SMEM>>>(
            MLP, w2B + (2 * l) * SW2, w2B + (2 * l + 1) * SW2,
            b2 + l * DM, X, X, TOK, DM, 4096);
    }

    logits_margin_k<<<TOK / 8, 256>>>(X, rfw, rfb, CH, FLAG, LIST, CNT);

    // ---- phase 2: exact FFMA recompute of flagged sequences ----
    gather_k<<<CMAX, 256>>>(x, LIST, CNT, XR);
    const int MR = CMAX * SEQ;   // 8192
    for (int l = 0; l < 2; l++) {
        ln_k<<<MR, 256>>>(XR, ln1_w + l * DM, ln1_b + l * DM, HR, CNT);
        fgemm_k<0><<<dim3(3072 / 128, MR / 128), 256>>>(
            HR, wqkv + l * SQKV, bqkv + l * 3072, nullptr, QKVR, MR, 3072, 1024, CNT);
        attn_k<<<CMAX * NH, 256>>>(QKVR, mask, HR, LIST, CNT);
        fgemm_k<2><<<dim3(DM / 128, MR / 128), 256>>>(
            HR, wo + l * SWO, bo + l * DM, XR, XR, MR, DM, 1024, CNT);
        ln_k<<<MR, 256>>>(XR, ln2_w + l * DM, ln2_b + l * DM, HR, CNT);
        fgemm_k<1><<<dim3(4096 / 128, MR / 128), 256>>>(
            HR, w1 + l * SW1, b1 + l * 4096, nullptr, MLPR, MR, 4096, 1024, CNT);
        fgemm_k<2><<<dim3(DM / 128, MR / 128), 256>>>(
            MLPR, w2 + l * SW2, b2 + l * DM, XR, XR, MR, DM, 4096, CNT);
    }
    logits_fix_k<<<MR / 8, 256>>>(XR, rfw, rfb, LIST, CNT, CH);

    // ---- pools + assembly ----
    maskmul_k<<<n4 / 256, 256>>>((const float4*)x, mask, (float4*)QKV, n4);
    tgemm_k<0><<<dim3(DM / 128, 16384 / 128), 256, TG_SMEM>>>(
        QKV, p2B, p2B + SP2, p2b, nullptr, P1, 16384, DM, 2048);
    tgemm_k<0><<<dim3(DM / 128, 8192 / 128), 256, TG_SMEM>>>(
        QKV, p4B, p4B + SP4, p4b, nullptr, P2, 8192, DM, 4096);

    msum_k<<<NSEQ, 32>>>(mask, MS);

    float* out = (float*)d_out;
    assemble_k<<<TOK, 256>>>(x, mask, CH, MS, P1, P2, femb, out, out + (size_t)TOK * DM);
    compress_k<<<NSEQ, 32>>>(CH, mask, out + (size_t)TOK * DM + TOK);
}